// round 6
// baseline (speedup 1.0000x reference)
#include <cuda_runtime.h>
#include <math.h>

#define NN 50000
#define EE 1600000

// ---------------- scratch (static device arrays; no allocation) ----------------
static __device__ float g_M[(size_t)NN * 512];   // [N,512] = X@Wx_cat + H@Wh_cat
static __device__ float g_W[256 * 512];          // packed [Wx;Wh] for 4 gates
static __device__ float g_deg[NN];
static __device__ float g_dis[NN];
static __device__ int   g_cnt[NN];
static __device__ int   g_cur[NN];
static __device__ int   g_rowoff[NN + 1];
static __device__ uint2 g_edata[EE];             // (src, bitcast(norm)) CSR-permuted
static __device__ int   g_is64;                  // 1 if edge_index really is int64

// ---------------- small helpers ----------------
__device__ __forceinline__ void fma2(unsigned long long& d, unsigned long long a,
                                     unsigned long long b) {
    asm("fma.rn.f32x2 %0, %1, %2, %3;" : "=l"(d) : "l"(a), "l"(b), "l"(d));
}
__device__ __forceinline__ unsigned long long dup2(float x) {
    unsigned long long r;
    asm("mov.b64 %0, {%1, %1};" : "=l"(r) : "f"(x));
    return r;
}
__device__ __forceinline__ float sigm(float x) { return 1.0f / (1.0f + expf(-x)); }

// read edge endpoint under either dtype layout
__device__ __forceinline__ int edge_src(const void* ei, int e, int is64) {
    if (is64) return (int)((const long long*)ei)[e];
    return ((const int*)ei)[e];
}
__device__ __forceinline__ int edge_dst(const void* ei, int e, int is64) {
    if (is64) return (int)((const long long*)ei)[(size_t)EE + e];
    return ((const int*)ei)[(size_t)EE + e];
}

// ---------------- kernels ----------------
// Detect int64 vs int32 edge_index. Reads only the first 4KB (in-bounds for both).
// For int32 data viewed as int64, the high word is a neighboring index -> value
// >= 2^32 (or generally outside [0,NN)) almost surely within 512 samples.
__global__ void detect_kernel(const void* ei) {
    const long long* p = (const long long*)ei;
    int ok = 1;
    for (int i = 0; i < 512; ++i) {
        long long v = p[i];
        if (v < 0 || v >= NN) ok = 0;
    }
    g_is64 = ok;
}

__global__ void zero_kernel() {
    int i = blockIdx.x * blockDim.x + threadIdx.x;
    if (i < NN) { g_deg[i] = 0.0f; g_cnt[i] = 0; g_cur[i] = 0; }
}

__global__ void pack_w_kernel(const float* __restrict__ wxi, const float* __restrict__ whi,
                              const float* __restrict__ wxf, const float* __restrict__ whf,
                              const float* __restrict__ wxc, const float* __restrict__ whc,
                              const float* __restrict__ wxo, const float* __restrict__ who) {
    int idx = blockIdx.x * blockDim.x + threadIdx.x;
    if (idx >= 256 * 512) return;
    int r = idx >> 9, c = idx & 511;
    int g = c >> 7, cc = c & 127;
    const float* W;
    int rr;
    if (r < 128) {
        W = (g == 0) ? wxi : (g == 1) ? wxf : (g == 2) ? wxc : wxo;
        rr = r;
    } else {
        W = (g == 0) ? whi : (g == 1) ? whf : (g == 2) ? whc : who;
        rr = r - 128;
    }
    g_W[idx] = W[rr * 128 + cc];
}

__global__ void deg_kernel(const void* __restrict__ ei, const float* __restrict__ w) {
    int e = blockIdx.x * blockDim.x + threadIdx.x;
    if (e >= EE) return;
    int is64 = g_is64;
    int dst = edge_dst(ei, e, is64);
    atomicAdd(&g_deg[dst], w[e]);
    atomicAdd(&g_cnt[dst], 1);
}

__global__ void dis_kernel() {
    int i = blockIdx.x * blockDim.x + threadIdx.x;
    if (i < NN) {
        float d = g_deg[i];
        g_dis[i] = (d > 0.0f) ? rsqrtf(d) : 0.0f;
    }
}

// exclusive scan of g_cnt -> g_rowoff, single block (1024 thr, shfl-based)
__global__ void scan_kernel() {
    __shared__ int wsum[32];
    __shared__ int wpref[32];
    int tid = threadIdx.x, lane = tid & 31, wid = tid >> 5;
    int carry = 0;
    for (int base = 0; base < NN; base += 1024) {
        int i = base + tid;
        int v = (i < NN) ? g_cnt[i] : 0;
        int x = v;
#pragma unroll
        for (int off = 1; off < 32; off <<= 1) {
            int t = __shfl_up_sync(0xffffffffu, x, off);
            if (lane >= off) x += t;
        }
        if (lane == 31) wsum[wid] = x;
        __syncthreads();
        if (wid == 0) {
            int y = wsum[lane];
#pragma unroll
            for (int off = 1; off < 32; off <<= 1) {
                int t = __shfl_up_sync(0xffffffffu, y, off);
                if (lane >= off) y += t;
            }
            wpref[lane] = y;
        }
        __syncthreads();
        int incl = x + ((wid > 0) ? wpref[wid - 1] : 0);
        if (i < NN) g_rowoff[i] = carry + incl - v;
        carry += wpref[31];
        __syncthreads();
    }
    if (tid == 0) g_rowoff[NN] = carry;
}

__global__ void build_kernel(const void* __restrict__ ei, const float* __restrict__ w) {
    int e = blockIdx.x * blockDim.x + threadIdx.x;
    if (e >= EE) return;
    int is64 = g_is64;
    int s = edge_src(ei, e, is64);
    int d = edge_dst(ei, e, is64);
    float nrm = g_dis[s] * w[e] * g_dis[d];
    int slot = g_rowoff[d] + atomicAdd(&g_cur[d], 1);
    g_edata[slot] = make_uint2((unsigned)s, __float_as_uint(nrm));
}

// M[N,512] = [X|H] @ g_W  — 128x128 tile, BK=8, 256 thr, 8x8 microtile via fma.f32x2
__global__ __launch_bounds__(256, 2) void gemm_kernel(const float* __restrict__ X,
                                                      const float* __restrict__ H) {
    __shared__ float As[8][128];  // As[k][m]
    __shared__ float Bs[8][128];  // Bs[k][n]
    int m0 = blockIdx.x * 128;
    int n0 = blockIdx.y * 128;
    int tid = threadIdx.x;
    int ty = tid >> 4, tx = tid & 15;

    unsigned long long acc[8][4];
#pragma unroll
    for (int i = 0; i < 8; i++)
#pragma unroll
        for (int j = 0; j < 4; j++) acc[i][j] = 0ull;

    int arow = tid >> 1;
    int acol = (tid & 1) * 4;
    int brow = tid >> 5;
    int bcol = (tid & 31) * 4;
    int gm_a = m0 + arow;

    for (int kt = 0; kt < 32; ++kt) {
        const float* Asrc = (kt < 16) ? X : H;
        int kc = (kt < 16) ? kt * 8 : (kt - 16) * 8;
        float4 av = make_float4(0.f, 0.f, 0.f, 0.f);
        if (gm_a < NN) av = *(const float4*)(Asrc + (size_t)gm_a * 128 + kc + acol);
        As[acol + 0][arow] = av.x;
        As[acol + 1][arow] = av.y;
        As[acol + 2][arow] = av.z;
        As[acol + 3][arow] = av.w;
        float4 bv = *(const float4*)(g_W + (kt * 8 + brow) * 512 + n0 + bcol);
        *(float4*)&Bs[brow][bcol] = bv;
        __syncthreads();
#pragma unroll
        for (int k = 0; k < 8; ++k) {
            float4 a0 = *(const float4*)&As[k][ty * 8];
            float4 a1 = *(const float4*)&As[k][ty * 8 + 4];
            unsigned long long a2[8];
            a2[0] = dup2(a0.x); a2[1] = dup2(a0.y); a2[2] = dup2(a0.z); a2[3] = dup2(a0.w);
            a2[4] = dup2(a1.x); a2[5] = dup2(a1.y); a2[6] = dup2(a1.z); a2[7] = dup2(a1.w);
            const unsigned long long* bp = (const unsigned long long*)&Bs[k][tx * 8];
            unsigned long long b0 = bp[0], b1 = bp[1], b2 = bp[2], b3 = bp[3];
#pragma unroll
            for (int i = 0; i < 8; i++) {
                fma2(acc[i][0], a2[i], b0);
                fma2(acc[i][1], a2[i], b1);
                fma2(acc[i][2], a2[i], b2);
                fma2(acc[i][3], a2[i], b3);
            }
        }
        __syncthreads();
    }
#pragma unroll
    for (int i = 0; i < 8; i++) {
        int gm = m0 + ty * 8 + i;
        if (gm < NN) {
            float* outp = g_M + (size_t)gm * 512 + n0 + tx * 8;
            union { unsigned long long u; float2 f; } c0, c1, c2, c3;
            c0.u = acc[i][0]; c1.u = acc[i][1]; c2.u = acc[i][2]; c3.u = acc[i][3];
            *(float4*)outp = make_float4(c0.f.x, c0.f.y, c1.f.x, c1.f.y);
            *(float4*)(outp + 4) = make_float4(c2.f.x, c2.f.y, c3.f.x, c3.f.y);
        }
    }
}

__device__ __forceinline__ void fm4(float4& a, float4 x, float w) {
    a.x += x.x * w; a.y += x.y * w; a.z += x.z * w; a.w += x.w * w;
}

// one warp per destination node (8 warps per block): gather+reduce over in-edges
// for all 512 channels, then fused gate math -> out (Hn block, then Cn block)
__global__ __launch_bounds__(256) void agg_gate_kernel(
        const float* __restrict__ C,
        const float* __restrict__ bxi, const float* __restrict__ bhi, const float* __restrict__ bi,
        const float* __restrict__ bxf, const float* __restrict__ bhf, const float* __restrict__ bf,
        const float* __restrict__ bxc, const float* __restrict__ bhc, const float* __restrict__ bc,
        const float* __restrict__ bxo, const float* __restrict__ bho, const float* __restrict__ bo,
        const float* __restrict__ wci, const float* __restrict__ wcf, const float* __restrict__ wco,
        float* __restrict__ out) {
    int n = blockIdx.x * 8 + (threadIdx.x >> 5);
    if (n >= NN) return;
    int lane = threadIdx.x & 31;  // owns channels lane*4..lane*4+3 per gate
    int beg = g_rowoff[n];
    int end = g_rowoff[n + 1];
    const float4* M4 = (const float4*)g_M;

    float4 ai = make_float4(0.f, 0.f, 0.f, 0.f);
    float4 af = ai, ac = ai, ao = ai;

    int j = beg;
    for (; j + 1 < end; j += 2) {
        uint2 e0 = g_edata[j];
        uint2 e1 = g_edata[j + 1];
        size_t r0 = (size_t)e0.x * 128 + lane;
        size_t r1 = (size_t)e1.x * 128 + lane;
        float w0 = __uint_as_float(e0.y);
        float w1 = __uint_as_float(e1.y);
        float4 x00 = M4[r0], x01 = M4[r0 + 32], x02 = M4[r0 + 64], x03 = M4[r0 + 96];
        float4 x10 = M4[r1], x11 = M4[r1 + 32], x12 = M4[r1 + 64], x13 = M4[r1 + 96];
        fm4(ai, x00, w0); fm4(af, x01, w0); fm4(ac, x02, w0); fm4(ao, x03, w0);
        fm4(ai, x10, w1); fm4(af, x11, w1); fm4(ac, x12, w1); fm4(ao, x13, w1);
    }
    if (j < end) {
        uint2 e0 = g_edata[j];
        size_t r0 = (size_t)e0.x * 128 + lane;
        float w0 = __uint_as_float(e0.y);
        float4 x00 = M4[r0], x01 = M4[r0 + 32], x02 = M4[r0 + 64], x03 = M4[r0 + 96];
        fm4(ai, x00, w0); fm4(af, x01, w0); fm4(ac, x02, w0); fm4(ao, x03, w0);
    }

    const float4* B4;
    float4 t;
    // combined biases per gate (all inputs summed): bx + bh + b
    B4 = (const float4*)bxi; float4 sbi = B4[lane];
    B4 = (const float4*)bhi; t = B4[lane]; sbi.x += t.x; sbi.y += t.y; sbi.z += t.z; sbi.w += t.w;
    B4 = (const float4*)bi;  t = B4[lane]; sbi.x += t.x; sbi.y += t.y; sbi.z += t.z; sbi.w += t.w;
    B4 = (const float4*)bxf; float4 sbf = B4[lane];
    B4 = (const float4*)bhf; t = B4[lane]; sbf.x += t.x; sbf.y += t.y; sbf.z += t.z; sbf.w += t.w;
    B4 = (const float4*)bf;  t = B4[lane]; sbf.x += t.x; sbf.y += t.y; sbf.z += t.z; sbf.w += t.w;
    B4 = (const float4*)bxc; float4 sbc = B4[lane];
    B4 = (const float4*)bhc; t = B4[lane]; sbc.x += t.x; sbc.y += t.y; sbc.z += t.z; sbc.w += t.w;
    B4 = (const float4*)bc;  t = B4[lane]; sbc.x += t.x; sbc.y += t.y; sbc.z += t.z; sbc.w += t.w;
    B4 = (const float4*)bxo; float4 sbo = B4[lane];
    B4 = (const float4*)bho; t = B4[lane]; sbo.x += t.x; sbo.y += t.y; sbo.z += t.z; sbo.w += t.w;
    B4 = (const float4*)bo;  t = B4[lane]; sbo.x += t.x; sbo.y += t.y; sbo.z += t.z; sbo.w += t.w;

    float4 wi4 = ((const float4*)wci)[lane];
    float4 wf4 = ((const float4*)wcf)[lane];
    float4 wo4 = ((const float4*)wco)[lane];
    float4 Cv = ((const float4*)C)[n * 32 + lane];

    float4 I, F, T, Cn, O, Hn;
    I.x = sigm(ai.x + sbi.x + wi4.x * Cv.x);
    I.y = sigm(ai.y + sbi.y + wi4.y * Cv.y);
    I.z = sigm(ai.z + sbi.z + wi4.z * Cv.z);
    I.w = sigm(ai.w + sbi.w + wi4.w * Cv.w);
    F.x = sigm(af.x + sbf.x + wf4.x * Cv.x);
    F.y = sigm(af.y + sbf.y + wf4.y * Cv.y);
    F.z = sigm(af.z + sbf.z + wf4.z * Cv.z);
    F.w = sigm(af.w + sbf.w + wf4.w * Cv.w);
    T.x = tanhf(ac.x + sbc.x);
    T.y = tanhf(ac.y + sbc.y);
    T.z = tanhf(ac.z + sbc.z);
    T.w = tanhf(ac.w + sbc.w);
    Cn.x = F.x * Cv.x + I.x * T.x;
    Cn.y = F.y * Cv.y + I.y * T.y;
    Cn.z = F.z * Cv.z + I.z * T.z;
    Cn.w = F.w * Cv.w + I.w * T.w;
    O.x = sigm(ao.x + sbo.x + wo4.x * Cn.x);
    O.y = sigm(ao.y + sbo.y + wo4.y * Cn.y);
    O.z = sigm(ao.z + sbo.z + wo4.z * Cn.z);
    O.w = sigm(ao.w + sbo.w + wo4.w * Cn.w);
    Hn.x = O.x * tanhf(Cn.x);
    Hn.y = O.y * tanhf(Cn.y);
    Hn.z = O.z * tanhf(Cn.z);
    Hn.w = O.w * tanhf(Cn.w);

    float4* out4 = (float4*)out;
    out4[n * 32 + lane] = Hn;                       // Hn block first
    out4[(size_t)NN * 32 + n * 32 + lane] = Cn;     // then Cn block
}

// ---------------- launch ----------------
extern "C" void kernel_launch(void* const* d_in, const int* in_sizes, int n_in,
                              void* d_out, int out_size) {
    (void)in_sizes; (void)n_in; (void)out_size;
    const float* X  = (const float*)d_in[0];
    const void*  EI = d_in[1];                 // int32 or int64 — detected on device
    const float* EW = (const float*)d_in[2];
    const float* H  = (const float*)d_in[3];
    const float* C  = (const float*)d_in[4];
    const float* Wx_i = (const float*)d_in[5];
    const float* bx_i = (const float*)d_in[6];
    const float* Wh_i = (const float*)d_in[7];
    const float* bh_i = (const float*)d_in[8];
    const float* Wx_f = (const float*)d_in[9];
    const float* bx_f = (const float*)d_in[10];
    const float* Wh_f = (const float*)d_in[11];
    const float* bh_f = (const float*)d_in[12];
    const float* Wx_c = (const float*)d_in[13];
    const float* bx_c = (const float*)d_in[14];
    const float* Wh_c = (const float*)d_in[15];
    const float* bh_c = (const float*)d_in[16];
    const float* Wx_o = (const float*)d_in[17];
    const float* bx_o = (const float*)d_in[18];
    const float* Wh_o = (const float*)d_in[19];
    const float* bh_o = (const float*)d_in[20];
    const float* wci  = (const float*)d_in[21];
    const float* wcf  = (const float*)d_in[22];
    const float* wco  = (const float*)d_in[23];
    const float* b_i  = (const float*)d_in[24];
    const float* b_f  = (const float*)d_in[25];
    const float* b_c  = (const float*)d_in[26];
    const float* b_o  = (const float*)d_in[27];
    float* out = (float*)d_out;

    detect_kernel<<<1, 1>>>(EI);
    zero_kernel<<<(NN + 255) / 256, 256>>>();
    pack_w_kernel<<<(256 * 512 + 255) / 256, 256>>>(Wx_i, Wh_i, Wx_f, Wh_f,
                                                    Wx_c, Wh_c, Wx_o, Wh_o);
    deg_kernel<<<(EE + 255) / 256, 256>>>(EI, EW);
    dis_kernel<<<(NN + 255) / 256, 256>>>();
    scan_kernel<<<1, 1024>>>();
    build_kernel<<<(EE + 255) / 256, 256>>>(EI, EW);
    dim3 gg((NN + 127) / 128, 4);
    gemm_kernel<<<gg, 256>>>(X, H);
    agg_gate_kernel<<<(NN + 7) / 8, 256>>>(C,
                                           bx_i, bh_i, b_i,
                                           bx_f, bh_f, b_f,
                                           bx_c, bh_c, b_c,
                                           bx_o, bh_o, b_o,
                                           wci, wcf, wco, out);
}

// round 7
// speedup vs baseline: 1.5100x; 1.5100x over previous
#include <cuda_runtime.h>
#include <math.h>

#define NN 50000
#define EE 1600000

// ---------------- scratch (static device arrays; no allocation) ----------------
static __device__ float g_G[(size_t)NN * 256];   // [N,256] = A_norm @ [X|H]
static __device__ float g_M[(size_t)NN * 512];   // [N,512] = G @ W_cat
static __device__ float g_W[256 * 512];          // packed [Wx;Wh] for 4 gates
static __device__ float g_deg[NN];
static __device__ float g_dis[NN];
static __device__ int   g_cnt[NN];
static __device__ int   g_cur[NN];
static __device__ int   g_rowoff[NN + 1];
static __device__ uint2 g_edata[EE];             // (src, bitcast(norm)) CSR-permuted
static __device__ int   g_is64;                  // 1 if edge_index really is int64

// ---------------- small helpers ----------------
__device__ __forceinline__ float sigm(float x) { return 1.0f / (1.0f + expf(-x)); }

__device__ __forceinline__ unsigned cvt_tf32(float f) {
    unsigned u;
    asm("cvt.rna.tf32.f32 %0, %1;" : "=r"(u) : "f"(f));
    return u;
}

__device__ __forceinline__ int edge_src(const void* ei, int e, int is64) {
    if (is64) return (int)((const long long*)ei)[e];
    return ((const int*)ei)[e];
}
__device__ __forceinline__ int edge_dst(const void* ei, int e, int is64) {
    if (is64) return (int)((const long long*)ei)[(size_t)EE + e];
    return ((const int*)ei)[(size_t)EE + e];
}

// ---------------- preprocessing kernels ----------------
__global__ void detect_kernel(const void* ei) {
    const long long* p = (const long long*)ei;
    int ok = 1;
    for (int i = 0; i < 512; ++i) {
        long long v = p[i];
        if (v < 0 || v >= NN) ok = 0;
    }
    g_is64 = ok;
}

__global__ void zero_kernel() {
    int i = blockIdx.x * blockDim.x + threadIdx.x;
    if (i < NN) { g_deg[i] = 0.0f; g_cnt[i] = 0; g_cur[i] = 0; }
}

__global__ void pack_w_kernel(const float* __restrict__ wxi, const float* __restrict__ whi,
                              const float* __restrict__ wxf, const float* __restrict__ whf,
                              const float* __restrict__ wxc, const float* __restrict__ whc,
                              const float* __restrict__ wxo, const float* __restrict__ who) {
    int idx = blockIdx.x * blockDim.x + threadIdx.x;
    if (idx >= 256 * 512) return;
    int r = idx >> 9, c = idx & 511;
    int g = c >> 7, cc = c & 127;
    const float* W;
    int rr;
    if (r < 128) {
        W = (g == 0) ? wxi : (g == 1) ? wxf : (g == 2) ? wxc : wxo;
        rr = r;
    } else {
        W = (g == 0) ? whi : (g == 1) ? whf : (g == 2) ? whc : who;
        rr = r - 128;
    }
    g_W[idx] = W[rr * 128 + cc];
}

__global__ void deg_kernel(const void* __restrict__ ei, const float* __restrict__ w) {
    int e = blockIdx.x * blockDim.x + threadIdx.x;
    if (e >= EE) return;
    int is64 = g_is64;
    int dst = edge_dst(ei, e, is64);
    atomicAdd(&g_deg[dst], w[e]);
    atomicAdd(&g_cnt[dst], 1);
}

__global__ void dis_kernel() {
    int i = blockIdx.x * blockDim.x + threadIdx.x;
    if (i < NN) {
        float d = g_deg[i];
        g_dis[i] = (d > 0.0f) ? rsqrtf(d) : 0.0f;
    }
}

// exclusive scan of g_cnt -> g_rowoff, single block (1024 thr, shfl-based)
__global__ void scan_kernel() {
    __shared__ int wsum[32];
    __shared__ int wpref[32];
    int tid = threadIdx.x, lane = tid & 31, wid = tid >> 5;
    int carry = 0;
    for (int base = 0; base < NN; base += 1024) {
        int i = base + tid;
        int v = (i < NN) ? g_cnt[i] : 0;
        int x = v;
#pragma unroll
        for (int off = 1; off < 32; off <<= 1) {
            int t = __shfl_up_sync(0xffffffffu, x, off);
            if (lane >= off) x += t;
        }
        if (lane == 31) wsum[wid] = x;
        __syncthreads();
        if (wid == 0) {
            int y = wsum[lane];
#pragma unroll
            for (int off = 1; off < 32; off <<= 1) {
                int t = __shfl_up_sync(0xffffffffu, y, off);
                if (lane >= off) y += t;
            }
            wpref[lane] = y;
        }
        __syncthreads();
        int incl = x + ((wid > 0) ? wpref[wid - 1] : 0);
        if (i < NN) g_rowoff[i] = carry + incl - v;
        carry += wpref[31];
        __syncthreads();
    }
    if (tid == 0) g_rowoff[NN] = carry;
}

__global__ void build_kernel(const void* __restrict__ ei, const float* __restrict__ w) {
    int e = blockIdx.x * blockDim.x + threadIdx.x;
    if (e >= EE) return;
    int is64 = g_is64;
    int s = edge_src(ei, e, is64);
    int d = edge_dst(ei, e, is64);
    float nrm = g_dis[s] * w[e] * g_dis[d];
    int slot = g_rowoff[d] + atomicAdd(&g_cur[d], 1);
    g_edata[slot] = make_uint2((unsigned)s, __float_as_uint(nrm));
}

// ---------------- aggregation BEFORE matmul: G[N,256] = A_norm @ [X|H] ---------
__device__ __forceinline__ void fm4(float4& a, float4 x, float w) {
    a.x += x.x * w; a.y += x.y * w; a.z += x.z * w; a.w += x.w * w;
}

__global__ __launch_bounds__(256) void agg_kernel(const float* __restrict__ X,
                                                  const float* __restrict__ H) {
    int n = blockIdx.x * 8 + (threadIdx.x >> 5);
    if (n >= NN) return;
    int lane = threadIdx.x & 31;   // owns 4 X-channels + 4 H-channels
    int beg = g_rowoff[n];
    int end = g_rowoff[n + 1];
    const float4* X4 = (const float4*)X;
    const float4* H4 = (const float4*)H;

    float4 ax = make_float4(0.f, 0.f, 0.f, 0.f);
    float4 ah = ax;

    int j = beg;
    for (; j + 1 < end; j += 2) {
        uint2 e0 = g_edata[j];
        uint2 e1 = g_edata[j + 1];
        size_t r0 = (size_t)e0.x * 32 + lane;
        size_t r1 = (size_t)e1.x * 32 + lane;
        float w0 = __uint_as_float(e0.y);
        float w1 = __uint_as_float(e1.y);
        float4 x0 = X4[r0], h0 = H4[r0];
        float4 x1 = X4[r1], h1 = H4[r1];
        fm4(ax, x0, w0); fm4(ah, h0, w0);
        fm4(ax, x1, w1); fm4(ah, h1, w1);
    }
    if (j < end) {
        uint2 e0 = g_edata[j];
        size_t r0 = (size_t)e0.x * 32 + lane;
        float w0 = __uint_as_float(e0.y);
        fm4(ax, X4[r0], w0); fm4(ah, H4[r0], w0);
    }

    float4* G4 = (float4*)g_G;
    G4[(size_t)n * 64 + lane] = ax;        // cols 0..127  (X part)
    G4[(size_t)n * 64 + 32 + lane] = ah;   // cols 128..255 (H part)
}

// ---------------- tf32 tensor-core GEMM: M[N,512] = G[N,256] @ W[256,512] ------
// BM=128, BN=128, BK=16; 8 warps (2x4), warp tile 64x32; mma.m16n8k8 tf32
__global__ __launch_bounds__(256) void gemm_kernel() {
    __shared__ unsigned As[16][132];   // [k][m], tf32 bits
    __shared__ unsigned Bs[16][132];   // [k][n], tf32 bits
    int m0 = blockIdx.x * 128;
    int n0 = blockIdx.y * 128;
    int tid = threadIdx.x;
    int warp = tid >> 5, lane = tid & 31;
    int wm = warp >> 2, wn = warp & 3;     // 2 x 4 warp grid
    int g = lane >> 2, tg = lane & 3;      // group (0..7), thread-in-group (0..3)

    float d[4][4][4];
#pragma unroll
    for (int mt = 0; mt < 4; ++mt)
#pragma unroll
        for (int nt = 0; nt < 4; ++nt)
#pragma unroll
            for (int i = 0; i < 4; ++i) d[mt][nt][i] = 0.0f;

    for (int kt = 0; kt < 16; ++kt) {
        // load A tile: 128 rows x 16 cols from g_G
#pragma unroll
        for (int s = 0; s < 2; ++s) {
            int slot = tid * 2 + s;           // 0..511
            int row = slot >> 2;
            int c4 = (slot & 3) * 4;
            int gr = m0 + row;
            float4 v = make_float4(0.f, 0.f, 0.f, 0.f);
            if (gr < NN) v = *(const float4*)(g_G + (size_t)gr * 256 + kt * 16 + c4);
            As[c4 + 0][row] = cvt_tf32(v.x);
            As[c4 + 1][row] = cvt_tf32(v.y);
            As[c4 + 2][row] = cvt_tf32(v.z);
            As[c4 + 3][row] = cvt_tf32(v.w);
        }
        // load B tile: 16 rows x 128 cols from g_W
#pragma unroll
        for (int s = 0; s < 2; ++s) {
            int slot = tid * 2 + s;
            int row = slot >> 5;              // 0..15
            int c4 = (slot & 31) * 4;
            float4 v = *(const float4*)(g_W + (size_t)(kt * 16 + row) * 512 + n0 + c4);
            Bs[row][c4 + 0] = cvt_tf32(v.x);
            Bs[row][c4 + 1] = cvt_tf32(v.y);
            Bs[row][c4 + 2] = cvt_tf32(v.z);
            Bs[row][c4 + 3] = cvt_tf32(v.w);
        }
        __syncthreads();
#pragma unroll
        for (int ks = 0; ks < 2; ++ks) {
            int k0 = ks * 8;
            unsigned a[4][4];
#pragma unroll
            for (int mt = 0; mt < 4; ++mt) {
                int mb = wm * 64 + mt * 16;
                a[mt][0] = As[k0 + tg][mb + g];
                a[mt][1] = As[k0 + tg][mb + g + 8];
                a[mt][2] = As[k0 + tg + 4][mb + g];
                a[mt][3] = As[k0 + tg + 4][mb + g + 8];
            }
            unsigned b[4][2];
#pragma unroll
            for (int nt = 0; nt < 4; ++nt) {
                int nb = wn * 32 + nt * 8;
                b[nt][0] = Bs[k0 + tg][nb + g];
                b[nt][1] = Bs[k0 + tg + 4][nb + g];
            }
#pragma unroll
            for (int mt = 0; mt < 4; ++mt)
#pragma unroll
                for (int nt = 0; nt < 4; ++nt) {
                    asm volatile(
                        "mma.sync.aligned.m16n8k8.row.col.f32.tf32.tf32.f32 "
                        "{%0,%1,%2,%3}, {%4,%5,%6,%7}, {%8,%9}, {%0,%1,%2,%3};"
                        : "+f"(d[mt][nt][0]), "+f"(d[mt][nt][1]),
                          "+f"(d[mt][nt][2]), "+f"(d[mt][nt][3])
                        : "r"(a[mt][0]), "r"(a[mt][1]), "r"(a[mt][2]), "r"(a[mt][3]),
                          "r"(b[nt][0]), "r"(b[nt][1]));
                }
        }
        __syncthreads();
    }
    // epilogue: c0=(g, tg*2), c1=(g, tg*2+1), c2=(g+8, tg*2), c3=(g+8, tg*2+1)
#pragma unroll
    for (int mt = 0; mt < 4; ++mt) {
        int r0 = m0 + wm * 64 + mt * 16 + g;
        int r1 = r0 + 8;
#pragma unroll
        for (int nt = 0; nt < 4; ++nt) {
            int c = n0 + wn * 32 + nt * 8 + tg * 2;
            if (r0 < NN)
                *(float2*)(g_M + (size_t)r0 * 512 + c) = make_float2(d[mt][nt][0], d[mt][nt][1]);
            if (r1 < NN)
                *(float2*)(g_M + (size_t)r1 * 512 + c) = make_float2(d[mt][nt][2], d[mt][nt][3]);
        }
    }
}

// ---------------- fused gate elementwise pass ----------------------------------
__global__ __launch_bounds__(256) void gate_kernel(
        const float* __restrict__ C,
        const float* __restrict__ bxi, const float* __restrict__ bhi, const float* __restrict__ bi,
        const float* __restrict__ bxf, const float* __restrict__ bhf, const float* __restrict__ bf,
        const float* __restrict__ bxc, const float* __restrict__ bhc, const float* __restrict__ bc,
        const float* __restrict__ bxo, const float* __restrict__ bho, const float* __restrict__ bo,
        const float* __restrict__ wci, const float* __restrict__ wcf, const float* __restrict__ wco,
        float* __restrict__ out) {
    int gid = blockIdx.x * 256 + threadIdx.x;
    if (gid >= NN * 32) return;
    int n = gid >> 5, lane = gid & 31;

    const float4* M4 = (const float4*)g_M;
    size_t r = (size_t)n * 128 + lane;
    float4 ai = M4[r], af = M4[r + 32], ac = M4[r + 64], ao = M4[r + 96];

    const float4* B4;
    float4 t;
    B4 = (const float4*)bxi; float4 sbi = B4[lane];
    B4 = (const float4*)bhi; t = B4[lane]; sbi.x += t.x; sbi.y += t.y; sbi.z += t.z; sbi.w += t.w;
    B4 = (const float4*)bi;  t = B4[lane]; sbi.x += t.x; sbi.y += t.y; sbi.z += t.z; sbi.w += t.w;
    B4 = (const float4*)bxf; float4 sbf = B4[lane];
    B4 = (const float4*)bhf; t = B4[lane]; sbf.x += t.x; sbf.y += t.y; sbf.z += t.z; sbf.w += t.w;
    B4 = (const float4*)bf;  t = B4[lane]; sbf.x += t.x; sbf.y += t.y; sbf.z += t.z; sbf.w += t.w;
    B4 = (const float4*)bxc; float4 sbc = B4[lane];
    B4 = (const float4*)bhc; t = B4[lane]; sbc.x += t.x; sbc.y += t.y; sbc.z += t.z; sbc.w += t.w;
    B4 = (const float4*)bc;  t = B4[lane]; sbc.x += t.x; sbc.y += t.y; sbc.z += t.z; sbc.w += t.w;
    B4 = (const float4*)bxo; float4 sbo = B4[lane];
    B4 = (const float4*)bho; t = B4[lane]; sbo.x += t.x; sbo.y += t.y; sbo.z += t.z; sbo.w += t.w;
    B4 = (const float4*)bo;  t = B4[lane]; sbo.x += t.x; sbo.y += t.y; sbo.z += t.z; sbo.w += t.w;

    float4 wi4 = ((const float4*)wci)[lane];
    float4 wf4 = ((const float4*)wcf)[lane];
    float4 wo4 = ((const float4*)wco)[lane];
    float4 Cv = ((const float4*)C)[(size_t)n * 32 + lane];

    float4 I, F, T, Cn, O, Hn;
    I.x = sigm(ai.x + sbi.x + wi4.x * Cv.x);
    I.y = sigm(ai.y + sbi.y + wi4.y * Cv.y);
    I.z = sigm(ai.z + sbi.z + wi4.z * Cv.z);
    I.w = sigm(ai.w + sbi.w + wi4.w * Cv.w);
    F.x = sigm(af.x + sbf.x + wf4.x * Cv.x);
    F.y = sigm(af.y + sbf.y + wf4.y * Cv.y);
    F.z = sigm(af.z + sbf.z + wf4.z * Cv.z);
    F.w = sigm(af.w + sbf.w + wf4.w * Cv.w);
    T.x = tanhf(ac.x + sbc.x);
    T.y = tanhf(ac.y + sbc.y);
    T.z = tanhf(ac.z + sbc.z);
    T.w = tanhf(ac.w + sbc.w);
    Cn.x = F.x * Cv.x + I.x * T.x;
    Cn.y = F.y * Cv.y + I.y * T.y;
    Cn.z = F.z * Cv.z + I.z * T.z;
    Cn.w = F.w * Cv.w + I.w * T.w;
    O.x = sigm(ao.x + sbo.x + wo4.x * Cn.x);
    O.y = sigm(ao.y + sbo.y + wo4.y * Cn.y);
    O.z = sigm(ao.z + sbo.z + wo4.z * Cn.z);
    O.w = sigm(ao.w + sbo.w + wo4.w * Cn.w);
    Hn.x = O.x * tanhf(Cn.x);
    Hn.y = O.y * tanhf(Cn.y);
    Hn.z = O.z * tanhf(Cn.z);
    Hn.w = O.w * tanhf(Cn.w);

    float4* out4 = (float4*)out;
    out4[(size_t)n * 32 + lane] = Hn;                       // Hn block first
    out4[(size_t)NN * 32 + (size_t)n * 32 + lane] = Cn;     // then Cn block
}

// ---------------- launch ----------------
extern "C" void kernel_launch(void* const* d_in, const int* in_sizes, int n_in,
                              void* d_out, int out_size) {
    (void)in_sizes; (void)n_in; (void)out_size;
    const float* X  = (const float*)d_in[0];
    const void*  EI = d_in[1];                 // int32 or int64 — detected on device
    const float* EW = (const float*)d_in[2];
    const float* H  = (const float*)d_in[3];
    const float* C  = (const float*)d_in[4];
    const float* Wx_i = (const float*)d_in[5];
    const float* bx_i = (const float*)d_in[6];
    const float* Wh_i = (const float*)d_in[7];
    const float* bh_i = (const float*)d_in[8];
    const float* Wx_f = (const float*)d_in[9];
    const float* bx_f = (const float*)d_in[10];
    const float* Wh_f = (const float*)d_in[11];
    const float* bh_f = (const float*)d_in[12];
    const float* Wx_c = (const float*)d_in[13];
    const float* bx_c = (const float*)d_in[14];
    const float* Wh_c = (const float*)d_in[15];
    const float* bh_c = (const float*)d_in[16];
    const float* Wx_o = (const float*)d_in[17];
    const float* bx_o = (const float*)d_in[18];
    const float* Wh_o = (const float*)d_in[19];
    const float* bh_o = (const float*)d_in[20];
    const float* wci  = (const float*)d_in[21];
    const float* wcf  = (const float*)d_in[22];
    const float* wco  = (const float*)d_in[23];
    const float* b_i  = (const float*)d_in[24];
    const float* b_f  = (const float*)d_in[25];
    const float* b_c  = (const float*)d_in[26];
    const float* b_o  = (const float*)d_in[27];
    float* out = (float*)d_out;

    detect_kernel<<<1, 1>>>(EI);
    zero_kernel<<<(NN + 255) / 256, 256>>>();
    pack_w_kernel<<<(256 * 512 + 255) / 256, 256>>>(Wx_i, Wh_i, Wx_f, Wh_f,
                                                    Wx_c, Wh_c, Wx_o, Wh_o);
    deg_kernel<<<(EE + 255) / 256, 256>>>(EI, EW);
    dis_kernel<<<(NN + 255) / 256, 256>>>();
    scan_kernel<<<1, 1024>>>();
    build_kernel<<<(EE + 255) / 256, 256>>>(EI, EW);
    agg_kernel<<<(NN + 7) / 8, 256>>>(X, H);
    dim3 gg((NN + 127) / 128, 4);
    gemm_kernel<<<gg, 256>>>();
    gate_kernel<<<(NN * 32 + 255) / 256, 256>>>(C,
                                                bx_i, bh_i, b_i,
                                                bx_f, bh_f, b_f,
                                                bx_c, bh_c, b_c,
                                                bx_o, bh_o, b_o,
                                                wci, wcf, wco, out);
}

// round 9
// speedup vs baseline: 1.7566x; 1.1633x over previous
#include <cuda_runtime.h>
#include <cuda_fp16.h>
#include <math.h>
#include <string.h>

#define NN 50000
#define EE 1600000
#define DEG_SCALE 67108864.0f          /* 2^26 fixed-point for packed deg */

// ---------------- scratch (static device arrays; no allocation) ----------------
static __device__ __align__(16) __half g_XH[(size_t)NN * 256];  // [N, X(128)|H(128)] fp16
static __device__ float g_G[(size_t)NN * 256];   // [N,256] = A_norm @ [X|H]
static __device__ float g_M[(size_t)NN * 512];   // [N,512] = G @ W_cat
static __device__ float g_W[256 * 512];          // packed [Wx;Wh] for 4 gates
static __device__ unsigned long long g_degcnt[NN];  // low40: deg fixed-point, high: cnt
static __device__ float g_dis[NN];
static __device__ int   g_cnt[NN];
static __device__ int   g_cur[NN];
static __device__ int   g_rowoff[NN + 1];
static __device__ uint2 g_edata[EE];             // (src, bitcast(norm)) CSR-permuted
static __device__ int   g_is64;                  // 1 if edge_index really is int64

// ---------------- small helpers ----------------
__device__ __forceinline__ float sigm(float x) { return 1.0f / (1.0f + expf(-x)); }

__device__ __forceinline__ unsigned h2_bits(__half2 h) {
    unsigned u;
    memcpy(&u, &h, sizeof(u));
    return u;
}

__device__ __forceinline__ unsigned cvt_tf32(float f) {
    unsigned u;
    asm("cvt.rna.tf32.f32 %0, %1;" : "=r"(u) : "f"(f));
    return u;
}

__device__ __forceinline__ int edge_src(const void* ei, int e, int is64) {
    if (is64) return (int)((const long long*)ei)[e];
    return ((const int*)ei)[e];
}
__device__ __forceinline__ int edge_dst(const void* ei, int e, int is64) {
    if (is64) return (int)((const long long*)ei)[(size_t)EE + e];
    return ((const int*)ei)[(size_t)EE + e];
}

// ---------------- preprocessing kernels ----------------
// Parallel dtype detection: 512 threads, 1 int64-view load each (first 4KB, in
// bounds for both dtypes). int32 data viewed as int64 packs a neighboring index
// into the high word -> value outside [0,NN) almost surely among 512 samples.
__global__ void detect_kernel(const void* ei) {
    __shared__ int bad;
    if (threadIdx.x == 0) bad = 0;
    __syncthreads();
    long long v = ((const long long*)ei)[threadIdx.x];
    if (v < 0 || v >= NN) bad = 1;   // benign race, any writer sets 1
    __syncthreads();
    if (threadIdx.x == 0) g_is64 = !bad;
}

__global__ void zero_kernel() {
    int i = blockIdx.x * blockDim.x + threadIdx.x;
    if (i < NN) { g_degcnt[i] = 0ull; g_cur[i] = 0; }
}

__global__ void pack_w_kernel(const float* __restrict__ wxi, const float* __restrict__ whi,
                              const float* __restrict__ wxf, const float* __restrict__ whf,
                              const float* __restrict__ wxc, const float* __restrict__ whc,
                              const float* __restrict__ wxo, const float* __restrict__ who) {
    int idx = blockIdx.x * blockDim.x + threadIdx.x;
    if (idx >= 256 * 512) return;
    int r = idx >> 9, c = idx & 511;
    int g = c >> 7, cc = c & 127;
    const float* W;
    int rr;
    if (r < 128) {
        W = (g == 0) ? wxi : (g == 1) ? wxf : (g == 2) ? wxc : wxo;
        rr = r;
    } else {
        W = (g == 0) ? whi : (g == 1) ? whf : (g == 2) ? whc : who;
        rr = r - 128;
    }
    g_W[idx] = W[rr * 128 + cc];
}

// pack [X|H] row-major into fp16: lane<16 -> X channels, lane>=16 -> H channels
__global__ __launch_bounds__(256) void xh_pack_kernel(const float* __restrict__ X,
                                                      const float* __restrict__ H) {
    int gid = blockIdx.x * 256 + threadIdx.x;
    if (gid >= NN * 32) return;
    int n = gid >> 5, lane = gid & 31;
    float4 a, b;
    if (lane < 16) {
        a = ((const float4*)X)[(size_t)n * 32 + lane * 2];
        b = ((const float4*)X)[(size_t)n * 32 + lane * 2 + 1];
    } else {
        int l = lane - 16;
        a = ((const float4*)H)[(size_t)n * 32 + l * 2];
        b = ((const float4*)H)[(size_t)n * 32 + l * 2 + 1];
    }
    uint4 o;
    o.x = h2_bits(__floats2half2_rn(a.x, a.y));
    o.y = h2_bits(__floats2half2_rn(a.z, a.w));
    o.z = h2_bits(__floats2half2_rn(b.x, b.y));
    o.w = h2_bits(__floats2half2_rn(b.z, b.w));
    ((uint4*)g_XH)[(size_t)n * 32 + lane] = o;
}

// one packed 64-bit atomic per edge: +1 in high bits, fixed-point weight in low
__global__ void deg_kernel(const void* __restrict__ ei, const float* __restrict__ w) {
    int e = blockIdx.x * blockDim.x + threadIdx.x;
    if (e >= EE) return;
    int is64 = g_is64;
    int dst = edge_dst(ei, e, is64);
    unsigned fx = __float2uint_rn(w[e] * DEG_SCALE);
    atomicAdd(&g_degcnt[dst], (1ull << 40) + (unsigned long long)fx);
}

__global__ void dis_kernel() {
    int i = blockIdx.x * blockDim.x + threadIdx.x;
    if (i < NN) {
        unsigned long long pc = g_degcnt[i];
        float d = (float)(double)(pc & ((1ull << 40) - 1)) * (1.0f / DEG_SCALE);
        g_cnt[i] = (int)(pc >> 40);
        g_dis[i] = (d > 0.0f) ? rsqrtf(d) : 0.0f;
    }
}

// exclusive scan of g_cnt -> g_rowoff, single block (1024 thr, shfl-based)
__global__ void scan_kernel() {
    __shared__ int wsum[32];
    __shared__ int wpref[32];
    int tid = threadIdx.x, lane = tid & 31, wid = tid >> 5;
    int carry = 0;
    for (int base = 0; base < NN; base += 1024) {
        int i = base + tid;
        int v = (i < NN) ? g_cnt[i] : 0;
        int x = v;
#pragma unroll
        for (int off = 1; off < 32; off <<= 1) {
            int t = __shfl_up_sync(0xffffffffu, x, off);
            if (lane >= off) x += t;
        }
        if (lane == 31) wsum[wid] = x;
        __syncthreads();
        if (wid == 0) {
            int y = wsum[lane];
#pragma unroll
            for (int off = 1; off < 32; off <<= 1) {
                int t = __shfl_up_sync(0xffffffffu, y, off);
                if (lane >= off) y += t;
            }
            wpref[lane] = y;
        }
        __syncthreads();
        int incl = x + ((wid > 0) ? wpref[wid - 1] : 0);
        if (i < NN) g_rowoff[i] = carry + incl - v;
        carry += wpref[31];
        __syncthreads();
    }
    if (tid == 0) g_rowoff[NN] = carry;
}

__global__ void build_kernel(const void* __restrict__ ei, const float* __restrict__ w) {
    int e = blockIdx.x * blockDim.x + threadIdx.x;
    if (e >= EE) return;
    int is64 = g_is64;
    int s = edge_src(ei, e, is64);
    int d = edge_dst(ei, e, is64);
    float nrm = g_dis[s] * w[e] * g_dis[d];
    int slot = g_rowoff[d] + atomicAdd(&g_cur[d], 1);
    g_edata[slot] = make_uint2((unsigned)s, __float_as_uint(nrm));
}

// ---------------- aggregation (fp16 gather, fp32 accum): G = A_norm @ [X|H] ----
__global__ __launch_bounds__(256) void agg_kernel() {
    int n = blockIdx.x * 8 + (threadIdx.x >> 5);
    if (n >= NN) return;
    int lane = threadIdx.x & 31;   // owns combined channels lane*8 .. lane*8+7
    int beg = g_rowoff[n];
    int end = g_rowoff[n + 1];
    const uint4* XH4 = (const uint4*)g_XH;

    float acc[8];
#pragma unroll
    for (int i = 0; i < 8; i++) acc[i] = 0.0f;

    int j = beg;
    for (; j + 1 < end; j += 2) {
        uint2 e0 = g_edata[j];
        uint2 e1 = g_edata[j + 1];
        uint4 v0 = XH4[(size_t)e0.x * 32 + lane];
        uint4 v1 = XH4[(size_t)e1.x * 32 + lane];
        float w0 = __uint_as_float(e0.y);
        float w1 = __uint_as_float(e1.y);
        const __half2* h0 = (const __half2*)&v0;
        const __half2* h1 = (const __half2*)&v1;
#pragma unroll
        for (int q = 0; q < 4; q++) {
            float2 f0 = __half22float2(h0[q]);
            float2 f1 = __half22float2(h1[q]);
            acc[q * 2 + 0] += f0.x * w0 + f1.x * w1;
            acc[q * 2 + 1] += f0.y * w0 + f1.y * w1;
        }
    }
    if (j < end) {
        uint2 e0 = g_edata[j];
        uint4 v0 = XH4[(size_t)e0.x * 32 + lane];
        float w0 = __uint_as_float(e0.y);
        const __half2* h0 = (const __half2*)&v0;
#pragma unroll
        for (int q = 0; q < 4; q++) {
            float2 f0 = __half22float2(h0[q]);
            acc[q * 2 + 0] += f0.x * w0;
            acc[q * 2 + 1] += f0.y * w0;
        }
    }

    float4* G4 = (float4*)g_G;
    G4[(size_t)n * 64 + lane * 2] = make_float4(acc[0], acc[1], acc[2], acc[3]);
    G4[(size_t)n * 64 + lane * 2 + 1] = make_float4(acc[4], acc[5], acc[6], acc[7]);
}

// ---------------- tf32 tensor-core GEMM: M[N,512] = G[N,256] @ W[256,512] ------
// BM=128, BN=128, BK=16; 8 warps (2x4), warp tile 64x32; mma.m16n8k8 tf32
__global__ __launch_bounds__(256) void gemm_kernel() {
    __shared__ unsigned As[16][132];   // [k][m], tf32 bits
    __shared__ unsigned Bs[16][132];   // [k][n], tf32 bits
    int m0 = blockIdx.x * 128;
    int n0 = blockIdx.y * 128;
    int tid = threadIdx.x;
    int warp = tid >> 5, lane = tid & 31;
    int wm = warp >> 2, wn = warp & 3;     // 2 x 4 warp grid
    int g = lane >> 2, tg = lane & 3;      // group (0..7), thread-in-group (0..3)

    float d[4][4][4];
#pragma unroll
    for (int mt = 0; mt < 4; ++mt)
#pragma unroll
        for (int nt = 0; nt < 4; ++nt)
#pragma unroll
            for (int i = 0; i < 4; ++i) d[mt][nt][i] = 0.0f;

    for (int kt = 0; kt < 16; ++kt) {
#pragma unroll
        for (int s = 0; s < 2; ++s) {
            int slot = tid * 2 + s;           // 0..511
            int row = slot >> 2;
            int c4 = (slot & 3) * 4;
            int gr = m0 + row;
            float4 v = make_float4(0.f, 0.f, 0.f, 0.f);
            if (gr < NN) v = *(const float4*)(g_G + (size_t)gr * 256 + kt * 16 + c4);
            As[c4 + 0][row] = cvt_tf32(v.x);
            As[c4 + 1][row] = cvt_tf32(v.y);
            As[c4 + 2][row] = cvt_tf32(v.z);
            As[c4 + 3][row] = cvt_tf32(v.w);
        }
#pragma unroll
        for (int s = 0; s < 2; ++s) {
            int slot = tid * 2 + s;
            int row = slot >> 5;              // 0..15
            int c4 = (slot & 31) * 4;
            float4 v = *(const float4*)(g_W + (size_t)(kt * 16 + row) * 512 + n0 + c4);
            Bs[row][c4 + 0] = cvt_tf32(v.x);
            Bs[row][c4 + 1] = cvt_tf32(v.y);
            Bs[row][c4 + 2] = cvt_tf32(v.z);
            Bs[row][c4 + 3] = cvt_tf32(v.w);
        }
        __syncthreads();
#pragma unroll
        for (int ks = 0; ks < 2; ++ks) {
            int k0 = ks * 8;
            unsigned a[4][4];
#pragma unroll
            for (int mt = 0; mt < 4; ++mt) {
                int mb = wm * 64 + mt * 16;
                a[mt][0] = As[k0 + tg][mb + g];
                a[mt][1] = As[k0 + tg][mb + g + 8];
                a[mt][2] = As[k0 + tg + 4][mb + g];
                a[mt][3] = As[k0 + tg + 4][mb + g + 8];
            }
            unsigned b[4][2];
#pragma unroll
            for (int nt = 0; nt < 4; ++nt) {
                int nb = wn * 32 + nt * 8;
                b[nt][0] = Bs[k0 + tg][nb + g];
                b[nt][1] = Bs[k0 + tg + 4][nb + g];
            }
#pragma unroll
            for (int mt = 0; mt < 4; ++mt)
#pragma unroll
                for (int nt = 0; nt < 4; ++nt) {
                    asm volatile(
                        "mma.sync.aligned.m16n8k8.row.col.f32.tf32.tf32.f32 "
                        "{%0,%1,%2,%3}, {%4,%5,%6,%7}, {%8,%9}, {%0,%1,%2,%3};"
                        : "+f"(d[mt][nt][0]), "+f"(d[mt][nt][1]),
                          "+f"(d[mt][nt][2]), "+f"(d[mt][nt][3])
                        : "r"(a[mt][0]), "r"(a[mt][1]), "r"(a[mt][2]), "r"(a[mt][3]),
                          "r"(b[nt][0]), "r"(b[nt][1]));
                }
        }
        __syncthreads();
    }
#pragma unroll
    for (int mt = 0; mt < 4; ++mt) {
        int r0 = m0 + wm * 64 + mt * 16 + g;
        int r1 = r0 + 8;
#pragma unroll
        for (int nt = 0; nt < 4; ++nt) {
            int c = n0 + wn * 32 + nt * 8 + tg * 2;
            if (r0 < NN)
                *(float2*)(g_M + (size_t)r0 * 512 + c) = make_float2(d[mt][nt][0], d[mt][nt][1]);
            if (r1 < NN)
                *(float2*)(g_M + (size_t)r1 * 512 + c) = make_float2(d[mt][nt][2], d[mt][nt][3]);
        }
    }
}

// ---------------- fused gate elementwise pass ----------------------------------
__global__ __launch_bounds__(256) void gate_kernel(
        const float* __restrict__ C,
        const float* __restrict__ bxi, const float* __restrict__ bhi, const float* __restrict__ bi,
        const float* __restrict__ bxf, const float* __restrict__ bhf, const float* __restrict__ bf,
        const float* __restrict__ bxc, const float* __restrict__ bhc, const float* __restrict__ bc,
        const float* __restrict__ bxo, const float* __restrict__ bho, const float* __restrict__ bo,
        const float* __restrict__ wci, const float* __restrict__ wcf, const float* __restrict__ wco,
        float* __restrict__ out) {
    int gid = blockIdx.x * 256 + threadIdx.x;
    if (gid >= NN * 32) return;
    int n = gid >> 5, lane = gid & 31;

    const float4* M4 = (const float4*)g_M;
    size_t r = (size_t)n * 128 + lane;
    float4 ai = M4[r], af = M4[r + 32], ac = M4[r + 64], ao = M4[r + 96];

    const float4* B4;
    float4 t;
    B4 = (const float4*)bxi; float4 sbi = B4[lane];
    B4 = (const float4*)bhi; t = B4[lane]; sbi.x += t.x; sbi.y += t.y; sbi.z += t.z; sbi.w += t.w;
    B4 = (const float4*)bi;  t = B4[lane]; sbi.x += t.x; sbi.y += t.y; sbi.z += t.z; sbi.w += t.w;
    B4 = (const float4*)bxf; float4 sbf = B4[lane];
    B4 = (const float4*)bhf; t = B4[lane]; sbf.x += t.x; sbf.y += t.y; sbf.z += t.z; sbf.w += t.w;
    B4 = (const float4*)bf;  t = B4[lane]; sbf.x += t.x; sbf.y += t.y; sbf.z += t.z; sbf.w += t.w;
    B4 = (const float4*)bxc; float4 sbc = B4[lane];
    B4 = (const float4*)bhc; t = B4[lane]; sbc.x += t.x; sbc.y += t.y; sbc.z += t.z; sbc.w += t.w;
    B4 = (const float4*)bc;  t = B4[lane]; sbc.x += t.x; sbc.y += t.y; sbc.z += t.z; sbc.w += t.w;
    B4 = (const float4*)bxo; float4 sbo = B4[lane];
    B4 = (const float4*)bho; t = B4[lane]; sbo.x += t.x; sbo.y += t.y; sbo.z += t.z; sbo.w += t.w;
    B4 = (const float4*)bo;  t = B4[lane]; sbo.x += t.x; sbo.y += t.y; sbo.z += t.z; sbo.w += t.w;

    float4 wi4 = ((const float4*)wci)[lane];
    float4 wf4 = ((const float4*)wcf)[lane];
    float4 wo4 = ((const float4*)wco)[lane];
    float4 Cv = ((const float4*)C)[(size_t)n * 32 + lane];

    float4 I, F, T, Cn, O, Hn;
    I.x = sigm(ai.x + sbi.x + wi4.x * Cv.x);
    I.y = sigm(ai.y + sbi.y + wi4.y * Cv.y);
    I.z = sigm(ai.z + sbi.z + wi4.z * Cv.z);
    I.w = sigm(ai.w + sbi.w + wi4.w * Cv.w);
    F.x = sigm(af.x + sbf.x + wf4.x * Cv.x);
    F.y = sigm(af.y + sbf.y + wf4.y * Cv.y);
    F.z = sigm(af.z + sbf.z + wf4.z * Cv.z);
    F.w = sigm(af.w + sbf.w + wf4.w * Cv.w);
    T.x = tanhf(ac.x + sbc.x);
    T.y = tanhf(ac.y + sbc.y);
    T.z = tanhf(ac.z + sbc.z);
    T.w = tanhf(ac.w + sbc.w);
    Cn.x = F.x * Cv.x + I.x * T.x;
    Cn.y = F.y * Cv.y + I.y * T.y;
    Cn.z = F.z * Cv.z + I.z * T.z;
    Cn.w = F.w * Cv.w + I.w * T.w;
    O.x = sigm(ao.x + sbo.x + wo4.x * Cn.x);
    O.y = sigm(ao.y + sbo.y + wo4.y * Cn.y);
    O.z = sigm(ao.z + sbo.z + wo4.z * Cn.z);
    O.w = sigm(ao.w + sbo.w + wo4.w * Cn.w);
    Hn.x = O.x * tanhf(Cn.x);
    Hn.y = O.y * tanhf(Cn.y);
    Hn.z = O.z * tanhf(Cn.z);
    Hn.w = O.w * tanhf(Cn.w);

    float4* out4 = (float4*)out;
    out4[(size_t)n * 32 + lane] = Hn;                       // Hn block first
    out4[(size_t)NN * 32 + (size_t)n * 32 + lane] = Cn;     // then Cn block
}

// ---------------- launch ----------------
extern "C" void kernel_launch(void* const* d_in, const int* in_sizes, int n_in,
                              void* d_out, int out_size) {
    (void)in_sizes; (void)n_in; (void)out_size;
    const float* X  = (const float*)d_in[0];
    const void*  EI = d_in[1];                 // int32 or int64 — detected on device
    const float* EW = (const float*)d_in[2];
    const float* H  = (const float*)d_in[3];
    const float* C  = (const float*)d_in[4];
    const float* Wx_i = (const float*)d_in[5];
    const float* bx_i = (const float*)d_in[6];
    const float* Wh_i = (const float*)d_in[7];
    const float* bh_i = (const float*)d_in[8];
    const float* Wx_f = (const float*)d_in[9];
    const float* bx_f = (const float*)d_in[10];
    const float* Wh_f = (const float*)d_in[11];
    const float* bh_f = (const float*)d_in[12];
    const float* Wx_c = (const float*)d_in[13];
    const float* bx_c = (const float*)d_in[14];
    const float* Wh_c = (const float*)d_in[15];
    const float* bh_c = (const float*)d_in[16];
    const float* Wx_o = (const float*)d_in[17];
    const float* bx_o = (const float*)d_in[18];
    const float* Wh_o = (const float*)d_in[19];
    const float* bh_o = (const float*)d_in[20];
    const float* wci  = (const float*)d_in[21];
    const float* wcf  = (const float*)d_in[22];
    const float* wco  = (const float*)d_in[23];
    const float* b_i  = (const float*)d_in[24];
    const float* b_f  = (const float*)d_in[25];
    const float* b_c  = (const float*)d_in[26];
    const float* b_o  = (const float*)d_in[27];
    float* out = (float*)d_out;

    detect_kernel<<<1, 512>>>(EI);
    zero_kernel<<<(NN + 255) / 256, 256>>>();
    pack_w_kernel<<<(256 * 512 + 255) / 256, 256>>>(Wx_i, Wh_i, Wx_f, Wh_f,
                                                    Wx_c, Wh_c, Wx_o, Wh_o);
    xh_pack_kernel<<<(NN * 32 + 255) / 256, 256>>>(X, H);
    deg_kernel<<<(EE + 255) / 256, 256>>>(EI, EW);
    dis_kernel<<<(NN + 255) / 256, 256>>>();
    scan_kernel<<<1, 1024>>>();
    build_kernel<<<(EE + 255) / 256, 256>>>(EI, EW);
    agg_kernel<<<(NN + 7) / 8, 256>>>();
    dim3 gg((NN + 127) / 128, 4);
    gemm_kernel<<<gg, 256>>>();
    gate_kernel<<<(NN * 32 + 255) / 256, 256>>>(C,
                                                bx_i, bh_i, b_i,
                                                bx_f, bh_f, b_f,
                                                bx_c, bh_c, b_c,
                                                bx_o, bh_o, b_o,
                                                wci, wcf, wco, out);
}

// round 10
// speedup vs baseline: 2.2861x; 1.3015x over previous
#include <cuda_runtime.h>
#include <cuda_fp16.h>
#include <math.h>
#include <string.h>

#define NN 50000
#define EE 1600000
#define DEG_SCALE 67108864.0f          /* 2^26 fixed-point for packed deg */

// ---------------- scratch (static device arrays; no allocation) ----------------
static __device__ __align__(16) __half g_XH[(size_t)NN * 256];  // [N, X(128)|H(128)] fp16
static __device__ __align__(16) __half g_Gh[(size_t)NN * 256];  // [N,256] agg result, fp16
static __device__ float g_M[(size_t)NN * 512];   // [N,512] = G @ W_cat (fp32)
static __device__ __align__(16) __half g_Wh[512 * 256];  // W_cat^T: [n=512][k=256] fp16
static __device__ unsigned long long g_degcnt[NN];  // low40: deg fixed-point, high: cnt
static __device__ float g_dis[NN];
static __device__ int   g_cnt[NN];
static __device__ int   g_cur[NN];
static __device__ int   g_rowoff[NN + 1];
static __device__ uint2 g_edata[EE];             // (src, bitcast(norm)) CSR-permuted
static __device__ int   g_is64;                  // 1 if edge_index really is int64

// ---------------- small helpers ----------------
__device__ __forceinline__ float sigm(float x) { return 1.0f / (1.0f + expf(-x)); }

__device__ __forceinline__ unsigned h2_bits(__half2 h) {
    unsigned u;
    memcpy(&u, &h, sizeof(u));
    return u;
}

__device__ __forceinline__ int edge_src(const void* ei, int e, int is64) {
    if (is64) return (int)((const long long*)ei)[e];
    return ((const int*)ei)[e];
}
__device__ __forceinline__ int edge_dst(const void* ei, int e, int is64) {
    if (is64) return (int)((const long long*)ei)[(size_t)EE + e];
    return ((const int*)ei)[(size_t)EE + e];
}

// ---------------- preprocessing kernels ----------------
__global__ void detect_kernel(const void* ei) {
    __shared__ int bad;
    if (threadIdx.x == 0) bad = 0;
    __syncthreads();
    long long v = ((const long long*)ei)[threadIdx.x];
    if (v < 0 || v >= NN) bad = 1;   // benign race, any writer sets 1
    __syncthreads();
    if (threadIdx.x == 0) g_is64 = !bad;
}

__global__ void zero_kernel() {
    int i = blockIdx.x * blockDim.x + threadIdx.x;
    if (i < NN) { g_degcnt[i] = 0ull; g_cur[i] = 0; }
}

// pack [Wx;Wh] for 4 gates, transposed to [n=512][k=256], fp16
__global__ void pack_w_kernel(const float* __restrict__ wxi, const float* __restrict__ whi,
                              const float* __restrict__ wxf, const float* __restrict__ whf,
                              const float* __restrict__ wxc, const float* __restrict__ whc,
                              const float* __restrict__ wxo, const float* __restrict__ who) {
    int idx = blockIdx.x * blockDim.x + threadIdx.x;
    if (idx >= 256 * 512) return;
    int r = idx >> 9, c = idx & 511;   // r = k (0..255), c = n (0..511)
    int g = c >> 7, cc = c & 127;
    const float* W;
    int rr;
    if (r < 128) {
        W = (g == 0) ? wxi : (g == 1) ? wxf : (g == 2) ? wxc : wxo;
        rr = r;
    } else {
        W = (g == 0) ? whi : (g == 1) ? whf : (g == 2) ? whc : who;
        rr = r - 128;
    }
    g_Wh[c * 256 + r] = __float2half(W[rr * 128 + cc]);
}

// pack [X|H] row-major into fp16: lane<16 -> X channels, lane>=16 -> H channels
__global__ __launch_bounds__(256) void xh_pack_kernel(const float* __restrict__ X,
                                                      const float* __restrict__ H) {
    int gid = blockIdx.x * 256 + threadIdx.x;
    if (gid >= NN * 32) return;
    int n = gid >> 5, lane = gid & 31;
    float4 a, b;
    if (lane < 16) {
        a = ((const float4*)X)[(size_t)n * 32 + lane * 2];
        b = ((const float4*)X)[(size_t)n * 32 + lane * 2 + 1];
    } else {
        int l = lane - 16;
        a = ((const float4*)H)[(size_t)n * 32 + l * 2];
        b = ((const float4*)H)[(size_t)n * 32 + l * 2 + 1];
    }
    uint4 o;
    o.x = h2_bits(__floats2half2_rn(a.x, a.y));
    o.y = h2_bits(__floats2half2_rn(a.z, a.w));
    o.z = h2_bits(__floats2half2_rn(b.x, b.y));
    o.w = h2_bits(__floats2half2_rn(b.z, b.w));
    ((uint4*)g_XH)[(size_t)n * 32 + lane] = o;
}

// one packed 64-bit atomic per edge: +1 in high bits, fixed-point weight in low
__global__ void deg_kernel(const void* __restrict__ ei, const float* __restrict__ w) {
    int e = blockIdx.x * blockDim.x + threadIdx.x;
    if (e >= EE) return;
    int is64 = g_is64;
    int dst = edge_dst(ei, e, is64);
    unsigned fx = __float2uint_rn(w[e] * DEG_SCALE);
    atomicAdd(&g_degcnt[dst], (1ull << 40) + (unsigned long long)fx);
}

__global__ void dis_kernel() {
    int i = blockIdx.x * blockDim.x + threadIdx.x;
    if (i < NN) {
        unsigned long long pc = g_degcnt[i];
        float d = (float)(double)(pc & ((1ull << 40) - 1)) * (1.0f / DEG_SCALE);
        g_cnt[i] = (int)(pc >> 40);
        g_dis[i] = (d > 0.0f) ? rsqrtf(d) : 0.0f;
    }
}

// exclusive scan of g_cnt -> g_rowoff, single block (1024 thr, shfl-based)
__global__ void scan_kernel() {
    __shared__ int wsum[32];
    __shared__ int wpref[32];
    int tid = threadIdx.x, lane = tid & 31, wid = tid >> 5;
    int carry = 0;
    for (int base = 0; base < NN; base += 1024) {
        int i = base + tid;
        int v = (i < NN) ? g_cnt[i] : 0;
        int x = v;
#pragma unroll
        for (int off = 1; off < 32; off <<= 1) {
            int t = __shfl_up_sync(0xffffffffu, x, off);
            if (lane >= off) x += t;
        }
        if (lane == 31) wsum[wid] = x;
        __syncthreads();
        if (wid == 0) {
            int y = wsum[lane];
#pragma unroll
            for (int off = 1; off < 32; off <<= 1) {
                int t = __shfl_up_sync(0xffffffffu, y, off);
                if (lane >= off) y += t;
            }
            wpref[lane] = y;
        }
        __syncthreads();
        int incl = x + ((wid > 0) ? wpref[wid - 1] : 0);
        if (i < NN) g_rowoff[i] = carry + incl - v;
        carry += wpref[31];
        __syncthreads();
    }
    if (tid == 0) g_rowoff[NN] = carry;
}

__global__ void build_kernel(const void* __restrict__ ei, const float* __restrict__ w) {
    int e = blockIdx.x * blockDim.x + threadIdx.x;
    if (e >= EE) return;
    int is64 = g_is64;
    int s = edge_src(ei, e, is64);
    int d = edge_dst(ei, e, is64);
    float nrm = g_dis[s] * w[e] * g_dis[d];
    int slot = g_rowoff[d] + atomicAdd(&g_cur[d], 1);
    g_edata[slot] = make_uint2((unsigned)s, __float_as_uint(nrm));
}

// ---------------- aggregation (fp16 gather, fp32 accum -> fp16 out) ------------
__global__ __launch_bounds__(256) void agg_kernel() {
    int n = blockIdx.x * 8 + (threadIdx.x >> 5);
    if (n >= NN) return;
    int lane = threadIdx.x & 31;   // owns combined channels lane*8 .. lane*8+7
    int beg = g_rowoff[n];
    int end = g_rowoff[n + 1];
    const uint4* XH4 = (const uint4*)g_XH;

    float acc[8];
#pragma unroll
    for (int i = 0; i < 8; i++) acc[i] = 0.0f;

    int j = beg;
    for (; j + 1 < end; j += 2) {
        uint2 e0 = g_edata[j];
        uint2 e1 = g_edata[j + 1];
        uint4 v0 = XH4[(size_t)e0.x * 32 + lane];
        uint4 v1 = XH4[(size_t)e1.x * 32 + lane];
        float w0 = __uint_as_float(e0.y);
        float w1 = __uint_as_float(e1.y);
        const __half2* h0 = (const __half2*)&v0;
        const __half2* h1 = (const __half2*)&v1;
#pragma unroll
        for (int q = 0; q < 4; q++) {
            float2 f0 = __half22float2(h0[q]);
            float2 f1 = __half22float2(h1[q]);
            acc[q * 2 + 0] += f0.x * w0 + f1.x * w1;
            acc[q * 2 + 1] += f0.y * w0 + f1.y * w1;
        }
    }
    if (j < end) {
        uint2 e0 = g_edata[j];
        uint4 v0 = XH4[(size_t)e0.x * 32 + lane];
        float w0 = __uint_as_float(e0.y);
        const __half2* h0 = (const __half2*)&v0;
#pragma unroll
        for (int q = 0; q < 4; q++) {
            float2 f0 = __half22float2(h0[q]);
            acc[q * 2 + 0] += f0.x * w0;
            acc[q * 2 + 1] += f0.y * w0;
        }
    }

    uint4 o;
    o.x = h2_bits(__floats2half2_rn(acc[0], acc[1]));
    o.y = h2_bits(__floats2half2_rn(acc[2], acc[3]));
    o.z = h2_bits(__floats2half2_rn(acc[4], acc[5]));
    o.w = h2_bits(__floats2half2_rn(acc[6], acc[7]));
    ((uint4*)g_Gh)[(size_t)n * 32 + lane] = o;
}

// ---------------- fp16 tensor-core GEMM: M[N,512] = G[N,256] @ W[256,512] ------
// BM=128, BN=128, BK=32; 8 warps (2x4), warp tile 64x32; mma.m16n8k16 f16->f32
// As [m][40] fp16 (pad 32->40: fragment banks (20g+tg)%32 all distinct)
// Bs [n][40] fp16 (W stored transposed [n][k])
__global__ __launch_bounds__(256) void gemm_kernel() {
    __shared__ __half As[128][40];
    __shared__ __half Bs[128][40];
    int m0 = blockIdx.x * 128;
    int n0 = blockIdx.y * 128;
    int tid = threadIdx.x;
    int warp = tid >> 5, lane = tid & 31;
    int wm = warp >> 2, wn = warp & 3;     // 2 x 4 warp grid
    int g = lane >> 2, tg = lane & 3;      // group (0..7), thread-in-group (0..3)

    float d[4][4][4];
#pragma unroll
    for (int mt = 0; mt < 4; ++mt)
#pragma unroll
        for (int nt = 0; nt < 4; ++nt)
#pragma unroll
            for (int i = 0; i < 4; ++i) d[mt][nt][i] = 0.0f;

    for (int kt = 0; kt < 8; ++kt) {
        // A tile: 128 rows x 32 k (fp16), 2 x uint4 per thread
#pragma unroll
        for (int s = 0; s < 2; ++s) {
            int slot = tid * 2 + s;           // 0..511
            int row = slot >> 2;              // 0..127
            int c8 = (slot & 3) * 8;          // fp16 col 0,8,16,24
            int gr = m0 + row;
            uint4 v = make_uint4(0u, 0u, 0u, 0u);
            if (gr < NN)
                v = *(const uint4*)(g_Gh + (size_t)gr * 256 + kt * 32 + c8);
            *(uint4*)&As[row][c8] = v;
        }
        // B tile: 128 n-rows x 32 k (fp16), from W^T
#pragma unroll
        for (int s = 0; s < 2; ++s) {
            int slot = tid * 2 + s;
            int row = slot >> 2;              // n within tile
            int c8 = (slot & 3) * 8;
            uint4 v = *(const uint4*)(g_Wh + (size_t)(n0 + row) * 256 + kt * 32 + c8);
            *(uint4*)&Bs[row][c8] = v;
        }
        __syncthreads();
#pragma unroll
        for (int ks = 0; ks < 2; ++ks) {
            int k0 = ks * 16;
            unsigned a[4][4];
#pragma unroll
            for (int mt = 0; mt < 4; ++mt) {
                int mb = wm * 64 + mt * 16;
                a[mt][0] = *(const unsigned*)&As[mb + g][k0 + tg * 2];
                a[mt][1] = *(const unsigned*)&As[mb + g + 8][k0 + tg * 2];
                a[mt][2] = *(const unsigned*)&As[mb + g][k0 + tg * 2 + 8];
                a[mt][3] = *(const unsigned*)&As[mb + g + 8][k0 + tg * 2 + 8];
            }
            unsigned b[4][2];
#pragma unroll
            for (int nt = 0; nt < 4; ++nt) {
                int nb = wn * 32 + nt * 8;
                b[nt][0] = *(const unsigned*)&Bs[nb + g][k0 + tg * 2];
                b[nt][1] = *(const unsigned*)&Bs[nb + g][k0 + tg * 2 + 8];
            }
#pragma unroll
            for (int mt = 0; mt < 4; ++mt)
#pragma unroll
                for (int nt = 0; nt < 4; ++nt) {
                    asm volatile(
                        "mma.sync.aligned.m16n8k16.row.col.f32.f16.f16.f32 "
                        "{%0,%1,%2,%3}, {%4,%5,%6,%7}, {%8,%9}, {%0,%1,%2,%3};"
                        : "+f"(d[mt][nt][0]), "+f"(d[mt][nt][1]),
                          "+f"(d[mt][nt][2]), "+f"(d[mt][nt][3])
                        : "r"(a[mt][0]), "r"(a[mt][1]), "r"(a[mt][2]), "r"(a[mt][3]),
                          "r"(b[nt][0]), "r"(b[nt][1]));
                }
        }
        __syncthreads();
    }
#pragma unroll
    for (int mt = 0; mt < 4; ++mt) {
        int r0 = m0 + wm * 64 + mt * 16 + g;
        int r1 = r0 + 8;
#pragma unroll
        for (int nt = 0; nt < 4; ++nt) {
            int c = n0 + wn * 32 + nt * 8 + tg * 2;
            if (r0 < NN)
                *(float2*)(g_M + (size_t)r0 * 512 + c) = make_float2(d[mt][nt][0], d[mt][nt][1]);
            if (r1 < NN)
                *(float2*)(g_M + (size_t)r1 * 512 + c) = make_float2(d[mt][nt][2], d[mt][nt][3]);
        }
    }
}

// ---------------- fused gate elementwise pass ----------------------------------
__global__ __launch_bounds__(256) void gate_kernel(
        const float* __restrict__ C,
        const float* __restrict__ bxi, const float* __restrict__ bhi, const float* __restrict__ bi,
        const float* __restrict__ bxf, const float* __restrict__ bhf, const float* __restrict__ bf,
        const float* __restrict__ bxc, const float* __restrict__ bhc, const float* __restrict__ bc,
        const float* __restrict__ bxo, const float* __restrict__ bho, const float* __restrict__ bo,
        const float* __restrict__ wci, const float* __restrict__ wcf, const float* __restrict__ wco,
        float* __restrict__ out) {
    int gid = blockIdx.x * 256 + threadIdx.x;
    if (gid >= NN * 32) return;
    int n = gid >> 5, lane = gid & 31;

    const float4* M4 = (const float4*)g_M;
    size_t r = (size_t)n * 128 + lane;
    float4 ai = M4[r], af = M4[r + 32], ac = M4[r + 64], ao = M4[r + 96];

    const float4* B4;
    float4 t;
    B4 = (const float4*)bxi; float4 sbi = B4[lane];
    B4 = (const float4*)bhi; t = B4[lane]; sbi.x += t.x; sbi.y += t.y; sbi.z += t.z; sbi.w += t.w;
    B4 = (const float4*)bi;  t = B4[lane]; sbi.x += t.x; sbi.y += t.y; sbi.z += t.z; sbi.w += t.w;
    B4 = (const float4*)bxf; float4 sbf = B4[lane];
    B4 = (const float4*)bhf; t = B4[lane]; sbf.x += t.x; sbf.y += t.y; sbf.z += t.z; sbf.w += t.w;
    B4 = (const float4*)bf;  t = B4[lane]; sbf.x += t.x; sbf.y += t.y; sbf.z += t.z; sbf.w += t.w;
    B4 = (const float4*)bxc; float4 sbc = B4[lane];
    B4 = (const float4*)bhc; t = B4[lane]; sbc.x += t.x; sbc.y += t.y; sbc.z += t.z; sbc.w += t.w;
    B4 = (const float4*)bc;  t = B4[lane]; sbc.x += t.x; sbc.y += t.y; sbc.z += t.z; sbc.w += t.w;
    B4 = (const float4*)bxo; float4 sbo = B4[lane];
    B4 = (const float4*)bho; t = B4[lane]; sbo.x += t.x; sbo.y += t.y; sbo.z += t.z; sbo.w += t.w;
    B4 = (const float4*)bo;  t = B4[lane]; sbo.x += t.x; sbo.y += t.y; sbo.z += t.z; sbo.w += t.w;

    float4 wi4 = ((const float4*)wci)[lane];
    float4 wf4 = ((const float4*)wcf)[lane];
    float4 wo4 = ((const float4*)wco)[lane];
    float4 Cv = ((const float4*)C)[(size_t)n * 32 + lane];

    float4 I, F, T, Cn, O, Hn;
    I.x = sigm(ai.x + sbi.x + wi4.x * Cv.x);
    I.y = sigm(ai.y + sbi.y + wi4.y * Cv.y);
    I.z = sigm(ai.z + sbi.z + wi4.z * Cv.z);
    I.w = sigm(ai.w + sbi.w + wi4.w * Cv.w);
    F.x = sigm(af.x + sbf.x + wf4.x * Cv.x);
    F.y = sigm(af.y + sbf.y + wf4.y * Cv.y);
    F.z = sigm(af.z + sbf.z + wf4.z * Cv.z);
    F.w = sigm(af.w + sbf.w + wf4.w * Cv.w);
    T.x = tanhf(ac.x + sbc.x);
    T.y = tanhf(ac.y + sbc.y);
    T.z = tanhf(ac.z + sbc.z);
    T.w = tanhf(ac.w + sbc.w);
    Cn.x = F.x * Cv.x + I.x * T.x;
    Cn.y = F.y * Cv.y + I.y * T.y;
    Cn.z = F.z * Cv.z + I.z * T.z;
    Cn.w = F.w * Cv.w + I.w * T.w;
    O.x = sigm(ao.x + sbo.x + wo4.x * Cn.x);
    O.y = sigm(ao.y + sbo.y + wo4.y * Cn.y);
    O.z = sigm(ao.z + sbo.z + wo4.z * Cn.z);
    O.w = sigm(ao.w + sbo.w + wo4.w * Cn.w);
    Hn.x = O.x * tanhf(Cn.x);
    Hn.y = O.y * tanhf(Cn.y);
    Hn.z = O.z * tanhf(Cn.z);
    Hn.w = O.w * tanhf(Cn.w);

    float4* out4 = (float4*)out;
    out4[(size_t)n * 32 + lane] = Hn;                       // Hn block first
    out4[(size_t)NN * 32 + (size_t)n * 32 + lane] = Cn;     // then Cn block
}

// ---------------- launch ----------------
extern "C" void kernel_launch(void* const* d_in, const int* in_sizes, int n_in,
                              void* d_out, int out_size) {
    (void)in_sizes; (void)n_in; (void)out_size;
    const float* X  = (const float*)d_in[0];
    const void*  EI = d_in[1];                 // int32 or int64 — detected on device
    const float* EW = (const float*)d_in[2];
    const float* H  = (const float*)d_in[3];
    const float* C  = (const float*)d_in[4];
    const float* Wx_i = (const float*)d_in[5];
    const float* bx_i = (const float*)d_in[6];
    const float* Wh_i = (const float*)d_in[7];
    const float* bh_i = (const float*)d_in[8];
    const float* Wx_f = (const float*)d_in[9];
    const float* bx_f = (const float*)d_in[10];
    const float* Wh_f = (const float*)d_in[11];
    const float* bh_f = (const float*)d_in[12];
    const float* Wx_c = (const float*)d_in[13];
    const float* bx_c = (const float*)d_in[14];
    const float* Wh_c = (const float*)d_in[15];
    const float* bh_c = (const float*)d_in[16];
    const float* Wx_o = (const float*)d_in[17];
    const float* bx_o = (const float*)d_in[18];
    const float* Wh_o = (const float*)d_in[19];
    const float* bh_o = (const float*)d_in[20];
    const float* wci  = (const float*)d_in[21];
    const float* wcf  = (const float*)d_in[22];
    const float* wco  = (const float*)d_in[23];
    const float* b_i  = (const float*)d_in[24];
    const float* b_f  = (const float*)d_in[25];
    const float* b_c  = (const float*)d_in[26];
    const float* b_o  = (const float*)d_in[27];
    float* out = (float*)d_out;

    detect_kernel<<<1, 512>>>(EI);
    zero_kernel<<<(NN + 255) / 256, 256>>>();
    pack_w_kernel<<<(256 * 512 + 255) / 256, 256>>>(Wx_i, Wh_i, Wx_f, Wh_f,
                                                    Wx_c, Wh_c, Wx_o, Wh_o);
    xh_pack_kernel<<<(NN * 32 + 255) / 256, 256>>>(X, H);
    deg_kernel<<<(EE + 255) / 256, 256>>>(EI, EW);
    dis_kernel<<<(NN + 255) / 256, 256>>>();
    scan_kernel<<<1, 1024>>>();
    build_kernel<<<(EE + 255) / 256, 256>>>(EI, EW);
    agg_kernel<<<(NN + 7) / 8, 256>>>();
    dim3 gg((NN + 127) / 128, 4);
    gemm_kernel<<<gg, 256>>>();
    gate_kernel<<<(NN * 32 + 255) / 256, 256>>>(C,
                                                bx_i, bh_i, b_i,
                                                bx_f, bh_f, b_f,
                                                bx_c, bh_c, b_c,
                                                bx_o, bh_o, b_o,
                                                wci, wcf, wco, out);
}